// round 12
// baseline (speedup 1.0000x reference)
#include <cuda_runtime.h>
#include <cuda_fp16.h>
#include <math.h>
#include <stdint.h>

#define NTHR   256
#define GRID   304           // 2 CTAs/SM * 152 SMs
#define HW     65536

// ---------------------------------------------------------------------------
// Static device scratch. Planes are PRE-SHIFTED per channel group, so GEMM
// A-fills are plain aligned row copies (cp.async-able). Single fp16 precision
// (measured rel_err 3.5e-4, ~3x margin under the 1e-3 gate).
// ---------------------------------------------------------------------------
__device__ __half g_xs[(size_t)8 * 100 * HW];   // shifted x, fp16
__device__ __half g_hs[(size_t)8 * 200 * HW];   // shifted gelu(h), fp16
__device__ __align__(16) __half g_w1i[224 * 112];   // L1 weight image (50176 B)
__device__ __align__(16) __half g_w2i[112 * 208];   // L2 weight image (46592 B)

// B-panel swizzle (32B rows of 16 halfs), proven in rounds 5-11.
__host__ __device__ __forceinline__ int swz(int r, int k) {
    return (r >> 3) * 256 + (r & 7) * 32 + ((((k >> 3) ^ (r >> 2)) & 1) << 4) + (k & 7) * 2;
}

__device__ __forceinline__ uint32_t smem_u32(const void* p) {
    uint32_t a;
    asm("{ .reg .u64 t; cvta.to.shared.u64 t, %1; cvt.u32.u64 %0, t; }" : "=r"(a) : "l"(p));
    return a;
}
__device__ __forceinline__ void ldsm_x4t(uint32_t* r, uint32_t a) {
    asm volatile("ldmatrix.sync.aligned.m8n8.x4.trans.shared.b16 {%0,%1,%2,%3}, [%4];"
                 : "=r"(r[0]), "=r"(r[1]), "=r"(r[2]), "=r"(r[3]) : "r"(a));
}
__device__ __forceinline__ void ldsm_x4(uint32_t* r, uint32_t a) {
    asm volatile("ldmatrix.sync.aligned.m8n8.x4.shared.b16 {%0,%1,%2,%3}, [%4];"
                 : "=r"(r[0]), "=r"(r[1]), "=r"(r[2]), "=r"(r[3]) : "r"(a));
}
__device__ __forceinline__ void ldsm_x2(uint32_t* r, uint32_t a) {
    asm volatile("ldmatrix.sync.aligned.m8n8.x2.shared.b16 {%0,%1}, [%2];"
                 : "=r"(r[0]), "=r"(r[1]) : "r"(a));
}
__device__ __forceinline__ void mma_f16(float* d, const uint32_t* a, const uint32_t* b) {
    asm volatile(
        "mma.sync.aligned.m16n8k16.row.col.f32.f16.f16.f32 "
        "{%0,%1,%2,%3}, {%4,%5,%6,%7}, {%8,%9}, {%0,%1,%2,%3};"
        : "+f"(d[0]), "+f"(d[1]), "+f"(d[2]), "+f"(d[3])
        : "r"(a[0]), "r"(a[1]), "r"(a[2]), "r"(a[3]), "r"(b[0]), "r"(b[1]));
}
#define CP_ASYNC16(dst, src, sz) \
    asm volatile("cp.async.cg.shared.global [%0], [%1], 16, %2;" \
                 :: "r"(dst), "l"(src), "r"(sz))
#define CP_COMMIT()  asm volatile("cp.async.commit_group;" ::: "memory")
#define CP_WAIT0()   asm volatile("cp.async.wait_group 0;" ::: "memory")

// ---------------------------------------------------------------------------
// prep_x: build shifted fp16 plane from fp32 x. Four pixels per thread.
// groups of 20 channels: +x, -x, +y, -y, identity.
// ---------------------------------------------------------------------------
__global__ void prep_x(const float* __restrict__ x) {
    size_t i = (size_t)blockIdx.x * NTHR + threadIdx.x;
    if (i >= (size_t)8 * 100 * HW / 4) return;
    const int x4 = (int)(i & 63) * 4;
    const int y  = (int)(i >> 6) & 255;
    const int cb = (int)(i >> 14);           // b*100 + c
    const int c  = cb % 100;
    const int g  = c / 20;
    const int dy = (g == 2) - (g == 3);
    const int dx = (g == 0) - (g == 1);
    const int sy = y + dy;
    const float* row = x + (((size_t)cb) << 16) + (size_t)sy * 256;
    uint32_t v01 = 0, v23 = 0;
    #pragma unroll
    for (int j = 0; j < 4; j++) {
        int sx = x4 + j + dx;
        float v = ((unsigned)sy < 256u && (unsigned)sx < 256u) ? row[sx] : 0.0f;
        uint32_t h = __half_as_ushort(__float2half_rn(v));
        if (j < 2) v01 |= h << (16 * j); else v23 |= h << (16 * (j - 2));
    }
    size_t o = (((size_t)cb) << 16) + (size_t)y * 256 + x4;
    *(uint2*)(g_xs + o) = make_uint2(v01, v23);
}

// prep_w: fp16 swizzled weight panel images (zero-padded).
__global__ void prep_w(const float* __restrict__ w1, const float* __restrict__ w2) {
    int tid = blockIdx.x * blockDim.x + threadIdx.x;
    int nth = gridDim.x * blockDim.x;
    for (int i = tid; i < 224 * 112; i += nth) {
        int n = i / 112, k = i - n * 112;
        float v = (n < 200 && k < 100) ? w1[n * 100 + k] : 0.0f;
        *(__half*)((char*)g_w1i + (k >> 4) * 7168 + swz(n, k & 15)) = __float2half_rn(v);
    }
    for (int i = tid; i < 112 * 208; i += nth) {
        int n = i / 208, k = i - n * 208;
        float v = (n < 100 && k < 200) ? w2[n * 200 + k] : 0.0f;
        *(__half*)((char*)g_w2i + (k >> 4) * 3584 + swz(n, k & 15)) = __float2half_rn(v);
    }
}

// ---------------------------------------------------------------------------
// Persistent shift-GEMM. Tile = MPIX pixels of one (b, y) row.
// A smem: [SECS k-slots][MPIX fp16] rows, XOR-chunk swizzled, cp.async fill.
// B smem: weight image (ldmatrix, non-trans).
// L1 epilogue: GELU'd fp16 staged in smem [NOUT][68-px halo rows] (x-shift
// folded into stage index), then flushed as row-contiguous STG.16 pairs.
// ---------------------------------------------------------------------------
template<int CK, int SECS, int STEPS, int NOUT, int NPAD, int MPIX, int MWARPS,
         int MF, int BPANEL, int BBYTES, bool L1M>
__global__ __launch_bounds__(NTHR, 2) void shift_gemm(
    const __half* __restrict__ ph, const __half* __restrict__ bimg,
    const float* __restrict__ bias, float* __restrict__ out_)
{
    constexpr int NF = NPAD / ((8 / MWARPS) * 8);    // 7 both layers
    constexpr int WM = MF * 16;
    constexpr int WN = NF * 8;
    constexpr int ROWB = MPIX * 2;                   // bytes per k-slot row
    constexpr int NCH  = ROWB / 16;                  // 16B chunks per row
    constexpr int ABYTES = SECS * ROWB;
    constexpr int XT = 256 / MPIX;                   // x-tiles per image row
    constexpr int NTILES = XT * 256 * 8;
    constexpr int STG_HW = 68;                       // stage halo row: 68 halfs

    extern __shared__ __align__(16) unsigned char smem[];
    const uint32_t sbA = smem_u32(smem);
    const uint32_t sbB = sbA + ABYTES;
    __half* stage = (__half*)(smem + ABYTES + BBYTES);
    const int tid = threadIdx.x, wid = tid >> 5, lid = tid & 31;
    const int wm = wid % MWARPS, wn = wid / MWARPS;

    // Copy B image to smem (once)
    for (int i = tid * 16; i < BBYTES; i += NTHR * 16)
        *(uint4*)(smem + ABYTES + i) = *(const uint4*)((const char*)bimg + i);

    // A-fill: cp.async whole tile (shift already baked into the plane)
    auto fill = [&](int t) {
        const int x0 = (t % XT) * MPIX;
        const int y  = (t / XT) & 255;
        const int b  = t / (XT * 256);
        const size_t pbase = (((size_t)b * CK) << 16) + (size_t)y * 256 + x0;
        for (int j = tid; j < SECS * NCH; j += NTHR) {
            const int s = j / NCH, c = j % NCH;
            const __half* src = ph + pbase + (((size_t)s) << 16) + c * 8;
            const uint32_t dst = sbA + s * ROWB + (((c ^ (s & 7)) & (NCH - 1)) << 4);
            const int sz = (s < CK) ? 16 : 0;   // pad k-slots -> zero-fill
            CP_ASYNC16(dst, src, sz);
        }
        CP_COMMIT();
    };

    // ldmatrix lane bases
    const int lg = lid >> 3, lr = lid & 7;
    uint32_t aoff[MF];
    #pragma unroll
    for (int mf = 0; mf < MF; mf++) {
        const int m0 = wm * WM + mf * 16 + (lg & 1) * 8;
        aoff[mf] = sbA + (uint32_t)(((lg >> 1) * 8 + lr) * ROWB)
                 + (uint32_t)((((m0 >> 3) ^ lr) & (NCH - 1)) << 4);
    }
    uint32_t boff[NF / 2], boff2;
    {
        const int nrow = ((lid >> 4) & 1) * 8 + (lid & 7);
        const int kh   = (lid >> 3) & 1;
        #pragma unroll
        for (int p = 0; p < NF / 2; p++)
            boff[p] = sbB + swz(wn * WN + p * 16 + nrow, kh * 8);
        boff2 = sbB + swz(wn * WN + (NF / 2) * 16 + (lid & 7), kh * 8);
    }

    // Prologue: fill first tile
    if ((int)blockIdx.x < NTILES) fill(blockIdx.x);
    CP_WAIT0();
    __syncthreads();

    for (int t = blockIdx.x; t < NTILES; t += GRID) {
        const int x0 = (t % XT) * MPIX;
        const int y  = (t / XT) & 255;
        const int b  = t / (XT * 256);

        // ---- MMA mainloop ----
        float acc[MF][NF][4];
        #pragma unroll
        for (int mf = 0; mf < MF; mf++)
            #pragma unroll
            for (int nf = 0; nf < NF; nf++)
                #pragma unroll
                for (int q = 0; q < 4; q++) acc[mf][nf][q] = 0.0f;

        #pragma unroll 2
        for (int s = 0; s < STEPS; s++) {
            const uint32_t ap = (uint32_t)s * (16 * ROWB);
            const uint32_t bp = (uint32_t)s * BPANEL;

            uint32_t a[MF][4], bf[NF][2];
            #pragma unroll
            for (int mf = 0; mf < MF; mf++) ldsm_x4t(a[mf], aoff[mf] + ap);
            #pragma unroll
            for (int p = 0; p < NF / 2; p++) {
                uint32_t r[4];
                ldsm_x4(r, boff[p] + bp);
                bf[2 * p][0] = r[0]; bf[2 * p][1] = r[1];
                bf[2 * p + 1][0] = r[2]; bf[2 * p + 1][1] = r[3];
            }
            if (NF & 1) ldsm_x2(bf[NF - 1], boff2 + bp);

            #pragma unroll
            for (int mf = 0; mf < MF; mf++)
                #pragma unroll
                for (int nf = 0; nf < NF; nf++)
                    mma_f16(acc[mf][nf], a[mf], bf[nf]);
        }
        __syncthreads();              // all warps done reading A

        // ---- Prefetch next tile's A while epilogue runs ----
        if (t + GRID < NTILES) fill(t + GRID);

        // ---- Epilogue ----
        const int r  = lid >> 2;
        const int ci = lid & 3;
        if (L1M) {
            // Phase 1: GELU + stage into smem [o][68] with x-shift folded in
            #pragma unroll
            for (int nf = 0; nf < NF; nf++) {
                const int o0 = wn * WN + nf * 8 + ci * 2;
                if (o0 < NOUT) {
                    const float bi0 = __ldg(bias + o0);
                    const float bi1 = __ldg(bias + o0 + 1);
                    const int g0g = o0 / 40;       // o0, o0+1 same group (o0 even)
                    const int dx = (g0g == 0) - (g0g == 1);
                    #pragma unroll
                    for (int mf = 0; mf < MF; mf++) {
                        const float* d = acc[mf][nf];
                        #pragma unroll
                        for (int q = 0; q < 4; q++) {
                            const int o  = o0 + (q & 1);
                            const int xg = x0 + wm * WM + mf * 16 + r + (q >> 1) * 8;
                            float v = d[q] + ((q & 1) ? bi1 : bi0);
                            v = 0.5f * v * (1.0f + erff(v * 0.70710678118654752440f));
                            const int pl = xg - dx - x0 + 1;     // 0..65
                            stage[o * STG_HW + pl] = __float2half_rn(v);
                        }
                    }
                }
            }
            __syncthreads();
            // Phase 2: flush channel rows, contiguous stores
            for (int o = wid; o < NOUT; o += 8) {
                const int g  = o / 40;
                const int dx = (g == 0) - (g == 1);
                const int dy = (g == 2) - (g == 3);
                const int ty = y - dy;
                __half* base = (__half*)out_ + (((size_t)(b * NOUT + o)) << 16);
                if ((unsigned)ty < 256u) {
                    const int txA = (x0 - dx < 0) ? 0 : x0 - dx;
                    const int txB0 = x0 + MPIX - 1 - dx;
                    const int txB = (txB0 > 255) ? 255 : txB0;
                    const int cnt = txB - txA;
                    __half* rowp = base + (size_t)ty * 256;
                    #pragma unroll
                    for (int hh = 0; hh < 2; hh++) {
                        const int idx = lid + hh * 32;
                        if (idx <= cnt) {
                            const int tx = txA + idx;
                            rowp[tx] = stage[o * STG_HW + (tx - x0 + 1)];
                        }
                    }
                }
                // image-edge zeros (no writer exists for these positions)
                if (dx == 1 && x0 + MPIX == 256 && lid == 0)
                    base[(size_t)y * 256 + 255] = __ushort_as_half(0);
                if (dx == -1 && x0 == 0 && lid == 0)
                    base[(size_t)y * 256 + 0] = __ushort_as_half(0);
                if (dy == 1 && y == 255) {
                    base[(size_t)255 * 256 + x0 + lid]      = __ushort_as_half(0);
                    base[(size_t)255 * 256 + x0 + lid + 32] = __ushort_as_half(0);
                }
                if (dy == -1 && y == 0) {
                    base[(size_t)x0 + lid]      = __ushort_as_half(0);
                    base[(size_t)x0 + lid + 32] = __ushort_as_half(0);
                }
            }
        } else {
            #pragma unroll
            for (int nf = 0; nf < NF; nf++) {
                const int o0 = wn * WN + nf * 8 + ci * 2;
                if (o0 < NOUT) {
                    const float bi0 = __ldg(bias + o0);
                    const float bi1 = __ldg(bias + o0 + 1);
                    #pragma unroll
                    for (int mf = 0; mf < MF; mf++) {
                        const float* d = acc[mf][nf];
                        #pragma unroll
                        for (int q = 0; q < 4; q++) {
                            const int o  = o0 + (q & 1);
                            const int xg = x0 + wm * WM + mf * 16 + r + (q >> 1) * 8;
                            out_[(((size_t)(b * NOUT + o)) << 16) + (size_t)y * 256 + xg]
                                = d[q] + ((q & 1) ? bi1 : bi0);
                        }
                    }
                }
            }
        }

        CP_WAIT0();                   // next tile's A landed
        __syncthreads();
    }
}

// L1: MPIX=64  (8192 tiles) warps 2Mx4N, MF=2; staged fp16 epilogue
// L2: MPIX=128 (4096 tiles) warps 4Mx2N, MF=2; direct fp32 stores
static constexpr int SMEM1 = 112 * 128 + 50176 + 200 * 68 * 2;  // 91712
static constexpr int SMEM2 = 208 * 256 + 46592;                 // 99840
extern "C" void kernel_launch(void* const* d_in, const int* in_sizes, int n_in,
                              void* d_out, int out_size)
{
    const float* x  = (const float*)d_in[0];
    const float* w1 = (const float*)d_in[1];
    const float* b1 = (const float*)d_in[2];
    const float* w2 = (const float*)d_in[3];
    const float* b2 = (const float*)d_in[4];

    __half *xs, *hs, *w1i, *w2i;
    cudaGetSymbolAddress((void**)&xs, g_xs);
    cudaGetSymbolAddress((void**)&hs, g_hs);
    cudaGetSymbolAddress((void**)&w1i, g_w1i);
    cudaGetSymbolAddress((void**)&w2i, g_w2i);

    auto k1 = shift_gemm<100, 112, 7, 200, 224,  64, 2, 2, 7168, 50176, true >;
    auto k2 = shift_gemm<200, 208, 13, 100, 112, 128, 4, 2, 3584, 46592, false>;
    cudaFuncSetAttribute(k1, cudaFuncAttributeMaxDynamicSharedMemorySize, SMEM1);
    cudaFuncSetAttribute(k2, cudaFuncAttributeMaxDynamicSharedMemorySize, SMEM2);

    prep_x<<<(int)(((size_t)8 * 100 * HW / 4 + NTHR - 1) / NTHR), NTHR>>>(x);
    prep_w<<<64, 256>>>(w1, w2);
    k1<<<GRID, NTHR, SMEM1>>>(xs, w1i, b1, (float*)hs);
    k2<<<GRID, NTHR, SMEM2>>>(hs, w2i, b2, (float*)d_out);
}

// round 13
// speedup vs baseline: 1.2378x; 1.2378x over previous
#include <cuda_runtime.h>
#include <cuda_fp16.h>
#include <math.h>
#include <stdint.h>

#define NTHR   256
#define GRID   304           // 2 CTAs/SM * 152 SMs
#define HW     65536

// ---------------------------------------------------------------------------
// Static device scratch. Planes are PRE-SHIFTED per channel group.
// ---------------------------------------------------------------------------
__device__ __half g_xs[(size_t)8 * 100 * HW];   // shifted x, fp16
__device__ __half g_hs[(size_t)8 * 200 * HW];   // shifted gelu(h), fp16
__device__ __align__(16) __half g_w1i[224 * 112];   // L1 weight image (50176 B)
__device__ __align__(16) __half g_w2i[112 * 208];   // L2 weight image (46592 B)

__host__ __device__ __forceinline__ int swz(int r, int k) {
    return (r >> 3) * 256 + (r & 7) * 32 + ((((k >> 3) ^ (r >> 2)) & 1) << 4) + (k & 7) * 2;
}

__device__ __forceinline__ uint32_t smem_u32(const void* p) {
    uint32_t a;
    asm("{ .reg .u64 t; cvta.to.shared.u64 t, %1; cvt.u32.u64 %0, t; }" : "=r"(a) : "l"(p));
    return a;
}
__device__ __forceinline__ void ldsm_x4t(uint32_t* r, uint32_t a) {
    asm volatile("ldmatrix.sync.aligned.m8n8.x4.trans.shared.b16 {%0,%1,%2,%3}, [%4];"
                 : "=r"(r[0]), "=r"(r[1]), "=r"(r[2]), "=r"(r[3]) : "r"(a));
}
__device__ __forceinline__ void ldsm_x4(uint32_t* r, uint32_t a) {
    asm volatile("ldmatrix.sync.aligned.m8n8.x4.shared.b16 {%0,%1,%2,%3}, [%4];"
                 : "=r"(r[0]), "=r"(r[1]), "=r"(r[2]), "=r"(r[3]) : "r"(a));
}
__device__ __forceinline__ void ldsm_x2(uint32_t* r, uint32_t a) {
    asm volatile("ldmatrix.sync.aligned.m8n8.x2.shared.b16 {%0,%1}, [%2];"
                 : "=r"(r[0]), "=r"(r[1]) : "r"(a));
}
__device__ __forceinline__ void mma_f16(float* d, const uint32_t* a, const uint32_t* b) {
    asm volatile(
        "mma.sync.aligned.m16n8k16.row.col.f32.f16.f16.f32 "
        "{%0,%1,%2,%3}, {%4,%5,%6,%7}, {%8,%9}, {%0,%1,%2,%3};"
        : "+f"(d[0]), "+f"(d[1]), "+f"(d[2]), "+f"(d[3])
        : "r"(a[0]), "r"(a[1]), "r"(a[2]), "r"(a[3]), "r"(b[0]), "r"(b[1]));
}
#define CP_ASYNC16(dst, src, sz) \
    asm volatile("cp.async.cg.shared.global [%0], [%1], 16, %2;" \
                 :: "r"(dst), "l"(src), "r"(sz))
#define CP_COMMIT()  asm volatile("cp.async.commit_group;" ::: "memory")
#define CP_WAIT0()   asm volatile("cp.async.wait_group 0;" ::: "memory")

__device__ __forceinline__ __half gelu_h(float v) {
    return __float2half_rn(0.5f * v * (1.0f + erff(v * 0.70710678118654752440f)));
}

// ---------------------------------------------------------------------------
// prep_x / prep_w: unchanged (proven rounds 7-11)
// ---------------------------------------------------------------------------
__global__ void prep_x(const float* __restrict__ x) {
    size_t i = (size_t)blockIdx.x * NTHR + threadIdx.x;
    if (i >= (size_t)8 * 100 * HW / 4) return;
    const int x4 = (int)(i & 63) * 4;
    const int y  = (int)(i >> 6) & 255;
    const int cb = (int)(i >> 14);
    const int c  = cb % 100;
    const int g  = c / 20;
    const int dy = (g == 2) - (g == 3);
    const int dx = (g == 0) - (g == 1);
    const int sy = y + dy;
    const float* row = x + (((size_t)cb) << 16) + (size_t)sy * 256;
    uint32_t v01 = 0, v23 = 0;
    #pragma unroll
    for (int j = 0; j < 4; j++) {
        int sx = x4 + j + dx;
        float v = ((unsigned)sy < 256u && (unsigned)sx < 256u) ? row[sx] : 0.0f;
        uint32_t h = __half_as_ushort(__float2half_rn(v));
        if (j < 2) v01 |= h << (16 * j); else v23 |= h << (16 * (j - 2));
    }
    size_t o = (((size_t)cb) << 16) + (size_t)y * 256 + x4;
    *(uint2*)(g_xs + o) = make_uint2(v01, v23);
}

__global__ void prep_w(const float* __restrict__ w1, const float* __restrict__ w2) {
    int tid = blockIdx.x * blockDim.x + threadIdx.x;
    int nth = gridDim.x * blockDim.x;
    for (int i = tid; i < 224 * 112; i += nth) {
        int n = i / 112, k = i - n * 112;
        float v = (n < 200 && k < 100) ? w1[n * 100 + k] : 0.0f;
        *(__half*)((char*)g_w1i + (k >> 4) * 7168 + swz(n, k & 15)) = __float2half_rn(v);
    }
    for (int i = tid; i < 112 * 208; i += nth) {
        int n = i / 208, k = i - n * 208;
        float v = (n < 100 && k < 200) ? w2[n * 200 + k] : 0.0f;
        *(__half*)((char*)g_w2i + (k >> 4) * 3584 + swz(n, k & 15)) = __float2half_rn(v);
    }
}

// ---------------------------------------------------------------------------
// k1 TRANSPOSED: A = W1 image (M=224 ch), B = pixel tile (N=64).
// acc fragment: d0,d1 = adjacent pixels of one channel -> packed stores.
// dx==0 channels (80-199): direct aligned STG.32 to shifted plane.
// dx!=0 channels (0-79): smem stage (STS.32) + contiguous row flush.
// ---------------------------------------------------------------------------
static constexpr int K1_ABYTES = 112 * 128;     // 14336
static constexpr int K1_BBYTES = 50176;
static constexpr int K1_STAGEB = 80 * 68 * 2;   // 10880
static constexpr int SMEM_K1 = K1_ABYTES + K1_BBYTES + K1_STAGEB;  // 75392

__global__ __launch_bounds__(NTHR, 2) void shift_gemm1(
    const __half* __restrict__ ph, const __half* __restrict__ bimg,
    const float* __restrict__ bias, __half* __restrict__ outh)
{
    constexpr int STEPS = 7, CK = 100, SECS = 112;
    constexpr int ROWB = 128, NCH = 8, XT = 4, NTILES = 8192;

    extern __shared__ __align__(16) unsigned char smem[];
    const uint32_t sbA = smem_u32(smem);
    const uint32_t sbB = sbA + K1_ABYTES;
    __half* stage = (__half*)(smem + K1_ABYTES + K1_BBYTES);
    const int tid = threadIdx.x, wid = tid >> 5, lid = tid & 31;
    const int wm = wid & 1;        // channel-half warp (0-1)
    const int wn = wid >> 1;       // pixel warp (0-3)

    for (int i = tid * 16; i < K1_BBYTES; i += NTHR * 16)
        *(uint4*)(smem + K1_ABYTES + i) = *(const uint4*)((const char*)bimg + i);

    auto fill = [&](int t) {
        const int x0 = (t & 3) * 64;
        const int y  = (t >> 2) & 255;
        const int b  = t >> 10;
        const size_t pbase = (((size_t)b * CK) << 16) + (size_t)y * 256 + x0;
        for (int j = tid; j < SECS * NCH; j += NTHR) {
            const int s = j >> 3, c = j & 7;
            const __half* src = ph + pbase + (((size_t)s) << 16) + c * 8;
            const uint32_t dst = sbA + s * ROWB + (((c ^ (s & 7)) & 7) << 4);
            CP_ASYNC16(dst, src, (s < CK) ? 16 : 0);
        }
        CP_COMMIT();
    };

    // B-frag (activations) lane base: x4t, tiles (k0n0)(k8n0)(k0n8)(k8n8)
    const int lg = lid >> 3, lr = lid & 7;
    const int krow = (lg & 1) * 8 + lr;
    const int c0   = wn * 2 + (lg >> 1);               // pixel 16B chunk
    const uint32_t bA = sbA + (uint32_t)(krow * ROWB) + ((uint32_t)((c0 ^ (krow & 7)) & 7) << 4);

    // A-frag (weights) lane bases: non-trans x4, tiles (m0k0)(m8k0)(m0k8)(m8k8)
    const int arow_l = ((lid >> 3) & 1) * 8 + (lid & 7);
    const int kh     = (lid >> 4) & 1;
    uint32_t aoff[7];
    #pragma unroll
    for (int mf = 0; mf < 7; mf++)
        aoff[mf] = sbB + (uint32_t)swz(wm * 112 + mf * 16 + arow_l, kh * 8);

    if ((int)blockIdx.x < NTILES) fill(blockIdx.x);
    CP_WAIT0();
    __syncthreads();

    for (int t = blockIdx.x; t < NTILES; t += GRID) {
        const int x0 = (t & 3) * 64;
        const int y  = (t >> 2) & 255;
        const int b  = t >> 10;

        float acc[7][2][4];
        #pragma unroll
        for (int mf = 0; mf < 7; mf++)
            #pragma unroll
            for (int nf = 0; nf < 2; nf++)
                #pragma unroll
                for (int q = 0; q < 4; q++) acc[mf][nf][q] = 0.0f;

        #pragma unroll
        for (int s = 0; s < STEPS; s++) {
            uint32_t bf[4];
            ldsm_x4t(bf, bA + (uint32_t)s * (16 * ROWB));
            #pragma unroll
            for (int mf = 0; mf < 7; mf++) {
                uint32_t a[4];
                ldsm_x4(a, aoff[mf] + (uint32_t)s * 7168);
                mma_f16(acc[mf][0], a, bf + 0);
                mma_f16(acc[mf][1], a, bf + 2);
            }
        }
        __syncthreads();

        if (t + GRID < NTILES) fill(t + GRID);

        // ---- Epilogue phase 1: gelu, pack, direct-store or stage ----
        const int r  = lid >> 2;
        const int pxb = x0 + wn * 16 + 2 * (lid & 3);
        #pragma unroll
        for (int mf = 0; mf < 7; mf++) {
            const int chb = wm * 112 + mf * 16 + r;
            #pragma unroll
            for (int h2 = 0; h2 < 2; h2++) {
                const int ch = chb + 8 * h2;
                if (ch < 200) {
                    const float bi = __ldg(bias + ch);
                    const int g  = ch / 40;
                    const int dx = (g == 0) - (g == 1);
                    const int dy = (g == 2) - (g == 3);
                    #pragma unroll
                    for (int nf = 0; nf < 2; nf++) {
                        const int px = pxb + nf * 8;
                        const __half h0 = gelu_h(acc[mf][nf][h2 * 2 + 0] + bi);
                        const __half h1 = gelu_h(acc[mf][nf][h2 * 2 + 1] + bi);
                        const uint32_t pk = (uint32_t)__half_as_ushort(h0)
                                          | ((uint32_t)__half_as_ushort(h1) << 16);
                        if (dx == 0) {
                            const size_t base = ((size_t)(b * 200 + ch)) << 16;
                            const int ty = y - dy;
                            if ((unsigned)ty < 256u)
                                *(uint32_t*)(outh + base + (size_t)ty * 256 + px) = pk;
                            if ((dy == 1 && y == 255) || (dy == -1 && y == 0))
                                *(uint32_t*)(outh + base + (size_t)y * 256 + px) = 0u;
                        } else {
                            *(uint32_t*)(stage + ch * 68 + (px - x0)) = pk;
                        }
                    }
                }
            }
        }
        __syncthreads();

        // ---- Epilogue phase 2: flush x-shifted channels (0-79) ----
        for (int ch = wid; ch < 80; ch += 8) {
            const int dx = (ch < 40) ? 1 : -1;
            __half* rowp = outh + (((size_t)(b * 200 + ch)) << 16) + (size_t)y * 256;
            const int txA0 = x0 - dx;
            const int txA = (txA0 < 0) ? 0 : txA0;
            const int txB0 = x0 + 63 - dx;
            const int txB = (txB0 > 255) ? 255 : txB0;
            #pragma unroll
            for (int hh = 0; hh < 2; hh++) {
                const int tx = txA + lid + hh * 32;
                if (tx <= txB)
                    rowp[tx] = stage[ch * 68 + (tx + dx - x0)];
            }
            if (dx == 1 && x0 == 192 && lid == 0) rowp[255] = __ushort_as_half(0);
            if (dx == -1 && x0 == 0  && lid == 0) rowp[0]   = __ushort_as_half(0);
        }

        CP_WAIT0();
        __syncthreads();
    }
}

// ---------------------------------------------------------------------------
// k2: byte-identical to the passing round-11 kernel (direct fp32 epilogue)
// ---------------------------------------------------------------------------
static constexpr int SMEM_K2 = 208 * 256 + 46592;   // 99840

__global__ __launch_bounds__(NTHR, 2) void shift_gemm2(
    const __half* __restrict__ ph, const __half* __restrict__ bimg,
    const float* __restrict__ bias, float* __restrict__ out_)
{
    constexpr int CK = 200, SECS = 208, STEPS = 13, NOUT = 100;
    constexpr int MWARPS = 4, MF = 2, BPANEL = 3584, BBYTES = 46592;
    constexpr int NF = 7, WM = 32, WN = 56;
    constexpr int ROWB = 256, NCH = 16, ABYTES = SECS * ROWB;
    constexpr int NTILES = 2 * 256 * 8;

    extern __shared__ __align__(16) unsigned char smem[];
    const uint32_t sbA = smem_u32(smem);
    const uint32_t sbB = sbA + ABYTES;
    const int tid = threadIdx.x, wid = tid >> 5, lid = tid & 31;
    const int wm = wid % MWARPS, wn = wid / MWARPS;

    for (int i = tid * 16; i < BBYTES; i += NTHR * 16)
        *(uint4*)(smem + ABYTES + i) = *(const uint4*)((const char*)bimg + i);

    auto fill = [&](int t) {
        const int x0 = (t & 1) << 7;
        const int y  = (t >> 1) & 255;
        const int b  = t >> 9;
        const size_t pbase = (((size_t)b * CK) << 16) + (size_t)y * 256 + x0;
        for (int j = tid; j < SECS * NCH; j += NTHR) {
            const int s = j / NCH, c = j % NCH;
            const __half* src = ph + pbase + (((size_t)s) << 16) + c * 8;
            const uint32_t dst = sbA + s * ROWB + (((c ^ (s & 7)) & (NCH - 1)) << 4);
            CP_ASYNC16(dst, src, (s < CK) ? 16 : 0);
        }
        CP_COMMIT();
    };

    const int lg = lid >> 3, lr = lid & 7;
    uint32_t aoff[MF];
    #pragma unroll
    for (int mf = 0; mf < MF; mf++) {
        const int m0 = wm * WM + mf * 16 + (lg & 1) * 8;
        aoff[mf] = sbA + (uint32_t)(((lg >> 1) * 8 + lr) * ROWB)
                 + (uint32_t)((((m0 >> 3) ^ lr) & (NCH - 1)) << 4);
    }
    uint32_t boff[NF / 2], boff2;
    {
        const int nrow = ((lid >> 4) & 1) * 8 + (lid & 7);
        const int khb  = (lid >> 3) & 1;
        #pragma unroll
        for (int p = 0; p < NF / 2; p++)
            boff[p] = sbB + swz(wn * WN + p * 16 + nrow, khb * 8);
        boff2 = sbB + swz(wn * WN + (NF / 2) * 16 + (lid & 7), khb * 8);
    }

    if ((int)blockIdx.x < NTILES) fill(blockIdx.x);
    CP_WAIT0();
    __syncthreads();

    for (int t = blockIdx.x; t < NTILES; t += GRID) {
        const int x0 = (t & 1) << 7;
        const int y  = (t >> 1) & 255;
        const int b  = t >> 9;

        float acc[MF][NF][4];
        #pragma unroll
        for (int mf = 0; mf < MF; mf++)
            #pragma unroll
            for (int nf = 0; nf < NF; nf++)
                #pragma unroll
                for (int q = 0; q < 4; q++) acc[mf][nf][q] = 0.0f;

        #pragma unroll 2
        for (int s = 0; s < STEPS; s++) {
            const uint32_t ap = (uint32_t)s * (16 * ROWB);
            const uint32_t bp = (uint32_t)s * BPANEL;
            uint32_t a[MF][4], bf[NF][2];
            #pragma unroll
            for (int mf = 0; mf < MF; mf++) ldsm_x4t(a[mf], aoff[mf] + ap);
            #pragma unroll
            for (int p = 0; p < NF / 2; p++) {
                uint32_t rr[4];
                ldsm_x4(rr, boff[p] + bp);
                bf[2 * p][0] = rr[0]; bf[2 * p][1] = rr[1];
                bf[2 * p + 1][0] = rr[2]; bf[2 * p + 1][1] = rr[3];
            }
            ldsm_x2(bf[NF - 1], boff2 + bp);
            #pragma unroll
            for (int mf = 0; mf < MF; mf++)
                #pragma unroll
                for (int nf = 0; nf < NF; nf++)
                    mma_f16(acc[mf][nf], a[mf], bf[nf]);
        }
        __syncthreads();

        if (t + GRID < NTILES) fill(t + GRID);

        const int r  = lid >> 2;
        const int ci = lid & 3;
        #pragma unroll
        for (int nf = 0; nf < NF; nf++) {
            const int o0 = wn * WN + nf * 8 + ci * 2;
            if (o0 < NOUT) {
                const float bi0 = __ldg(bias + o0);
                const float bi1 = __ldg(bias + o0 + 1);
                #pragma unroll
                for (int mf = 0; mf < MF; mf++) {
                    const float* d = acc[mf][nf];
                    #pragma unroll
                    for (int q = 0; q < 4; q++) {
                        const int o  = o0 + (q & 1);
                        const int xg = x0 + wm * WM + mf * 16 + r + (q >> 1) * 8;
                        out_[(((size_t)(b * NOUT + o)) << 16) + (size_t)y * 256 + xg]
                            = d[q] + ((q & 1) ? bi1 : bi0);
                    }
                }
            }
        }

        CP_WAIT0();
        __syncthreads();
    }
}

extern "C" void kernel_launch(void* const* d_in, const int* in_sizes, int n_in,
                              void* d_out, int out_size)
{
    const float* x  = (const float*)d_in[0];
    const float* w1 = (const float*)d_in[1];
    const float* b1 = (const float*)d_in[2];
    const float* w2 = (const float*)d_in[3];
    const float* b2 = (const float*)d_in[4];

    __half *xs, *hs, *w1i, *w2i;
    cudaGetSymbolAddress((void**)&xs, g_xs);
    cudaGetSymbolAddress((void**)&hs, g_hs);
    cudaGetSymbolAddress((void**)&w1i, g_w1i);
    cudaGetSymbolAddress((void**)&w2i, g_w2i);

    cudaFuncSetAttribute(shift_gemm1, cudaFuncAttributeMaxDynamicSharedMemorySize, SMEM_K1);
    cudaFuncSetAttribute(shift_gemm2, cudaFuncAttributeMaxDynamicSharedMemorySize, SMEM_K2);

    prep_x<<<(int)(((size_t)8 * 100 * HW / 4 + NTHR - 1) / NTHR), NTHR>>>(x);
    prep_w<<<64, 256>>>(w1, w2);
    shift_gemm1<<<GRID, NTHR, SMEM_K1>>>(xs, w1i, b1, hs);
    shift_gemm2<<<GRID, NTHR, SMEM_K2>>>(hs, w2i, b2, (float*)d_out);
}

// round 15
// speedup vs baseline: 1.4450x; 1.1674x over previous
#include <cuda_runtime.h>
#include <cuda_fp16.h>
#include <math.h>
#include <stdint.h>

#define NTHR   256
#define GRID   304           // 2 CTAs/SM * 152 SMs
#define HW     65536

// ---------------------------------------------------------------------------
// Static device scratch. Planes are PRE-SHIFTED per channel group.
// ---------------------------------------------------------------------------
__device__ __half g_xs[(size_t)8 * 100 * HW];   // shifted x, fp16
__device__ __half g_hs[(size_t)8 * 200 * HW];   // shifted gelu(h), fp16
__device__ __align__(16) __half g_w1i[224 * 112];   // L1 weight image (50176 B)
__device__ __align__(16) __half g_w2i[112 * 208];   // L2 weight image (46592 B)

__host__ __device__ __forceinline__ int swz(int r, int k) {
    return (r >> 3) * 256 + (r & 7) * 32 + ((((k >> 3) ^ (r >> 2)) & 1) << 4) + (k & 7) * 2;
}

__device__ __forceinline__ uint32_t smem_u32(const void* p) {
    uint32_t a;
    asm("{ .reg .u64 t; cvta.to.shared.u64 t, %1; cvt.u32.u64 %0, t; }" : "=r"(a) : "l"(p));
    return a;
}
__device__ __forceinline__ void ldsm_x4t(uint32_t* r, uint32_t a) {
    asm volatile("ldmatrix.sync.aligned.m8n8.x4.trans.shared.b16 {%0,%1,%2,%3}, [%4];"
                 : "=r"(r[0]), "=r"(r[1]), "=r"(r[2]), "=r"(r[3]) : "r"(a));
}
__device__ __forceinline__ void ldsm_x4(uint32_t* r, uint32_t a) {
    asm volatile("ldmatrix.sync.aligned.m8n8.x4.shared.b16 {%0,%1,%2,%3}, [%4];"
                 : "=r"(r[0]), "=r"(r[1]), "=r"(r[2]), "=r"(r[3]) : "r"(a));
}
__device__ __forceinline__ void ldsm_x2(uint32_t* r, uint32_t a) {
    asm volatile("ldmatrix.sync.aligned.m8n8.x2.shared.b16 {%0,%1}, [%2];"
                 : "=r"(r[0]), "=r"(r[1]) : "r"(a));
}
__device__ __forceinline__ void mma_f16(float* d, const uint32_t* a, const uint32_t* b) {
    asm volatile(
        "mma.sync.aligned.m16n8k16.row.col.f32.f16.f16.f32 "
        "{%0,%1,%2,%3}, {%4,%5,%6,%7}, {%8,%9}, {%0,%1,%2,%3};"
        : "+f"(d[0]), "+f"(d[1]), "+f"(d[2]), "+f"(d[3])
        : "r"(a[0]), "r"(a[1]), "r"(a[2]), "r"(a[3]), "r"(b[0]), "r"(b[1]));
}
#define CP_ASYNC16(dst, src, sz) \
    asm volatile("cp.async.cg.shared.global [%0], [%1], 16, %2;" \
                 :: "r"(dst), "l"(src), "r"(sz))
#define CP_COMMIT()  asm volatile("cp.async.commit_group;" ::: "memory")
#define CP_WAIT0()   asm volatile("cp.async.wait_group 0;" ::: "memory")

// Fast GELU: tanh form with HW MUFU.TANH (|h| < 1 regime: <1e-4 abs deviation
// from exact erf form; fp16 rounding dominates the error budget).
__device__ __forceinline__ float gelu_f(float v) {
    float u = v * (0.7978845608028654f + 0.0356774081363001f * v * v);
    float t;
    asm("tanh.approx.f32 %0, %1;" : "=f"(t) : "f"(u));
    float hv = 0.5f * v;
    return fmaf(hv, t, hv);
}
// Pack two fp32 -> fp16x2 in one instruction.
__device__ __forceinline__ uint32_t pack_h2(float lo, float hi) {
    uint32_t r;
    asm("cvt.rn.f16x2.f32 %0, %1, %2;" : "=r"(r) : "f"(hi), "f"(lo));
    return r;
}

// ---------------------------------------------------------------------------
// prep_x / prep_w: unchanged (proven rounds 7-13)
// ---------------------------------------------------------------------------
__global__ void prep_x(const float* __restrict__ x) {
    size_t i = (size_t)blockIdx.x * NTHR + threadIdx.x;
    if (i >= (size_t)8 * 100 * HW / 4) return;
    const int x4 = (int)(i & 63) * 4;
    const int y  = (int)(i >> 6) & 255;
    const int cb = (int)(i >> 14);
    const int c  = cb % 100;
    const int g  = c / 20;
    const int dy = (g == 2) - (g == 3);
    const int dx = (g == 0) - (g == 1);
    const int sy = y + dy;
    const float* row = x + (((size_t)cb) << 16) + (size_t)sy * 256;
    uint32_t v01 = 0, v23 = 0;
    #pragma unroll
    for (int j = 0; j < 4; j++) {
        int sx = x4 + j + dx;
        float v = ((unsigned)sy < 256u && (unsigned)sx < 256u) ? row[sx] : 0.0f;
        uint32_t h = __half_as_ushort(__float2half_rn(v));
        if (j < 2) v01 |= h << (16 * j); else v23 |= h << (16 * (j - 2));
    }
    size_t o = (((size_t)cb) << 16) + (size_t)y * 256 + x4;
    *(uint2*)(g_xs + o) = make_uint2(v01, v23);
}

__global__ void prep_w(const float* __restrict__ w1, const float* __restrict__ w2) {
    int tid = blockIdx.x * blockDim.x + threadIdx.x;
    int nth = gridDim.x * blockDim.x;
    for (int i = tid; i < 224 * 112; i += nth) {
        int n = i / 112, k = i - n * 112;
        float v = (n < 200 && k < 100) ? w1[n * 100 + k] : 0.0f;
        *(__half*)((char*)g_w1i + (k >> 4) * 7168 + swz(n, k & 15)) = __float2half_rn(v);
    }
    for (int i = tid; i < 112 * 208; i += nth) {
        int n = i / 208, k = i - n * 208;
        float v = (n < 100 && k < 200) ? w2[n * 200 + k] : 0.0f;
        *(__half*)((char*)g_w2i + (k >> 4) * 3584 + swz(n, k & 15)) = __float2half_rn(v);
    }
}

// ---------------------------------------------------------------------------
// k1 TRANSPOSED: A = W1 image (M=224 ch), B = pixel tile (N=64).
// acc fragment: d0,d1 = adjacent pixels of one channel -> packed stores.
// dx==0 channels (80-199): direct aligned STG.32 to shifted plane.
// dx!=0 channels (0-79): smem stage (STS.32) + contiguous row flush.
// ---------------------------------------------------------------------------
static constexpr int K1_ABYTES = 112 * 128;     // 14336
static constexpr int K1_BBYTES = 50176;
static constexpr int K1_STAGEB = 80 * 68 * 2;   // 10880
static constexpr int SMEM_K1 = K1_ABYTES + K1_BBYTES + K1_STAGEB;  // 75392

__global__ __launch_bounds__(NTHR, 2) void shift_gemm1(
    const __half* __restrict__ ph, const __half* __restrict__ bimg,
    const float* __restrict__ bias, __half* __restrict__ outh)
{
    constexpr int STEPS = 7, CK = 100, SECS = 112;
    constexpr int ROWB = 128, NCH = 8, XT = 4, NTILES = 8192;

    extern __shared__ __align__(16) unsigned char smem[];
    const uint32_t sbA = smem_u32(smem);
    const uint32_t sbB = sbA + K1_ABYTES;
    __half* stage = (__half*)(smem + K1_ABYTES + K1_BBYTES);
    const int tid = threadIdx.x, wid = tid >> 5, lid = tid & 31;
    const int wm = wid & 1;        // channel-half warp (0-1)
    const int wn = wid >> 1;       // pixel warp (0-3)

    for (int i = tid * 16; i < K1_BBYTES; i += NTHR * 16)
        *(uint4*)(smem + K1_ABYTES + i) = *(const uint4*)((const char*)bimg + i);

    auto fill = [&](int t) {
        const int x0 = (t & 3) * 64;
        const int y  = (t >> 2) & 255;
        const int b  = t >> 10;
        const size_t pbase = (((size_t)b * CK) << 16) + (size_t)y * 256 + x0;
        for (int j = tid; j < SECS * NCH; j += NTHR) {
            const int s = j >> 3, c = j & 7;
            const __half* src = ph + pbase + (((size_t)s) << 16) + c * 8;
            const uint32_t dst = sbA + s * ROWB + (((c ^ (s & 7)) & 7) << 4);
            CP_ASYNC16(dst, src, (s < CK) ? 16 : 0);
        }
        CP_COMMIT();
    };

    // B-frag (activations) lane base: x4t, tiles (k0n0)(k8n0)(k0n8)(k8n8)
    const int lg = lid >> 3, lr = lid & 7;
    const int krow = (lg & 1) * 8 + lr;
    const int c0   = wn * 2 + (lg >> 1);               // pixel 16B chunk
    const uint32_t bA = sbA + (uint32_t)(krow * ROWB) + ((uint32_t)((c0 ^ (krow & 7)) & 7) << 4);

    // A-frag (weights) lane bases: non-trans x4, tiles (m0k0)(m8k0)(m0k8)(m8k8)
    const int arow_l = ((lid >> 3) & 1) * 8 + (lid & 7);
    const int kh     = (lid >> 4) & 1;
    uint32_t aoff[7];
    #pragma unroll
    for (int mf = 0; mf < 7; mf++)
        aoff[mf] = sbB + (uint32_t)swz(wm * 112 + mf * 16 + arow_l, kh * 8);

    if ((int)blockIdx.x < NTILES) fill(blockIdx.x);
    CP_WAIT0();
    __syncthreads();

    for (int t = blockIdx.x; t < NTILES; t += GRID) {
        const int x0 = (t & 3) * 64;
        const int y  = (t >> 2) & 255;
        const int b  = t >> 10;

        float acc[7][2][4];
        #pragma unroll
        for (int mf = 0; mf < 7; mf++)
            #pragma unroll
            for (int nf = 0; nf < 2; nf++)
                #pragma unroll
                for (int q = 0; q < 4; q++) acc[mf][nf][q] = 0.0f;

        #pragma unroll
        for (int s = 0; s < STEPS; s++) {
            uint32_t bf[4];
            ldsm_x4t(bf, bA + (uint32_t)s * (16 * ROWB));
            #pragma unroll
            for (int mf = 0; mf < 7; mf++) {
                uint32_t a[4];
                ldsm_x4(a, aoff[mf] + (uint32_t)s * 7168);
                mma_f16(acc[mf][0], a, bf + 0);
                mma_f16(acc[mf][1], a, bf + 2);
            }
        }
        __syncthreads();

        if (t + GRID < NTILES) fill(t + GRID);

        // ---- Epilogue phase 1: fast gelu, pack, direct-store or stage ----
        const int r  = lid >> 2;
        const int pxb = x0 + wn * 16 + 2 * (lid & 3);
        #pragma unroll
        for (int mf = 0; mf < 7; mf++) {
            const int chb = wm * 112 + mf * 16 + r;
            #pragma unroll
            for (int h2 = 0; h2 < 2; h2++) {
                const int ch = chb + 8 * h2;
                if (ch < 200) {
                    const float bi = __ldg(bias + ch);
                    const int g  = ch / 40;
                    const int dx = (g == 0) - (g == 1);
                    const int dy = (g == 2) - (g == 3);
                    #pragma unroll
                    for (int nf = 0; nf < 2; nf++) {
                        const int px = pxb + nf * 8;
                        const float v0 = gelu_f(acc[mf][nf][h2 * 2 + 0] + bi);
                        const float v1 = gelu_f(acc[mf][nf][h2 * 2 + 1] + bi);
                        const uint32_t pk = pack_h2(v0, v1);
                        if (dx == 0) {
                            const size_t base = ((size_t)(b * 200 + ch)) << 16;
                            const int ty = y - dy;
                            if ((unsigned)ty < 256u)
                                *(uint32_t*)(outh + base + (size_t)ty * 256 + px) = pk;
                            if ((dy == 1 && y == 255) || (dy == -1 && y == 0))
                                *(uint32_t*)(outh + base + (size_t)y * 256 + px) = 0u;
                        } else {
                            *(uint32_t*)(stage + ch * 68 + (px - x0)) = pk;
                        }
                    }
                }
            }
        }
        __syncthreads();

        // ---- Epilogue phase 2: flush x-shifted channels (0-79) ----
        for (int ch = wid; ch < 80; ch += 8) {
            const int dx = (ch < 40) ? 1 : -1;
            __half* rowp = outh + (((size_t)(b * 200 + ch)) << 16) + (size_t)y * 256;
            const int txA0 = x0 - dx;
            const int txA = (txA0 < 0) ? 0 : txA0;
            const int txB0 = x0 + 63 - dx;
            const int txB = (txB0 > 255) ? 255 : txB0;
            #pragma unroll
            for (int hh = 0; hh < 2; hh++) {
                const int tx = txA + lid + hh * 32;
                if (tx <= txB)
                    rowp[tx] = stage[ch * 68 + (tx + dx - x0)];
            }
            if (dx == 1 && x0 == 192 && lid == 0) rowp[255] = __ushort_as_half(0);
            if (dx == -1 && x0 == 0  && lid == 0) rowp[0]   = __ushort_as_half(0);
        }

        CP_WAIT0();
        __syncthreads();
    }
}

// ---------------------------------------------------------------------------
// k2: byte-identical to the passing round-11/13 kernel (direct fp32 epilogue)
// ---------------------------------------------------------------------------
static constexpr int SMEM_K2 = 208 * 256 + 46592;   // 99840

__global__ __launch_bounds__(NTHR, 2) void shift_gemm2(
    const __half* __restrict__ ph, const __half* __restrict__ bimg,
    const float* __restrict__ bias, float* __restrict__ out_)
{
    constexpr int CK = 200, SECS = 208, STEPS = 13, NOUT = 100;
    constexpr int MWARPS = 4, MF = 2, BPANEL = 3584, BBYTES = 46592;
    constexpr int NF = 7, WM = 32, WN = 56;
    constexpr int ROWB = 256, NCH = 16, ABYTES = SECS * ROWB;
    constexpr int NTILES = 2 * 256 * 8;

    extern __shared__ __align__(16) unsigned char smem[];
    const uint32_t sbA = smem_u32(smem);
    const uint32_t sbB = sbA + ABYTES;
    const int tid = threadIdx.x, wid = tid >> 5, lid = tid & 31;
    const int wm = wid % MWARPS, wn = wid / MWARPS;

    for (int i = tid * 16; i < BBYTES; i += NTHR * 16)
        *(uint4*)(smem + ABYTES + i) = *(const uint4*)((const char*)bimg + i);

    auto fill = [&](int t) {
        const int x0 = (t & 1) << 7;
        const int y  = (t >> 1) & 255;
        const int b  = t >> 9;
        const size_t pbase = (((size_t)b * CK) << 16) + (size_t)y * 256 + x0;
        for (int j = tid; j < SECS * NCH; j += NTHR) {
            const int s = j / NCH, c = j % NCH;
            const __half* src = ph + pbase + (((size_t)s) << 16) + c * 8;
            const uint32_t dst = sbA + s * ROWB + (((c ^ (s & 7)) & (NCH - 1)) << 4);
            CP_ASYNC16(dst, src, (s < CK) ? 16 : 0);
        }
        CP_COMMIT();
    };

    const int lg = lid >> 3, lr = lid & 7;
    uint32_t aoff[MF];
    #pragma unroll
    for (int mf = 0; mf < MF; mf++) {
        const int m0 = wm * WM + mf * 16 + (lg & 1) * 8;
        aoff[mf] = sbA + (uint32_t)(((lg >> 1) * 8 + lr) * ROWB)
                 + (uint32_t)((((m0 >> 3) ^ lr) & (NCH - 1)) << 4);
    }
    uint32_t boff[NF / 2], boff2;
    {
        const int nrow = ((lid >> 4) & 1) * 8 + (lid & 7);
        const int khb  = (lid >> 3) & 1;
        #pragma unroll
        for (int p = 0; p < NF / 2; p++)
            boff[p] = sbB + swz(wn * WN + p * 16 + nrow, khb * 8);
        boff2 = sbB + swz(wn * WN + (NF / 2) * 16 + (lid & 7), khb * 8);
    }

    if ((int)blockIdx.x < NTILES) fill(blockIdx.x);
    CP_WAIT0();
    __syncthreads();

    for (int t = blockIdx.x; t < NTILES; t += GRID) {
        const int x0 = (t & 1) << 7;
        const int y  = (t >> 1) & 255;
        const int b  = t >> 9;

        float acc[MF][NF][4];
        #pragma unroll
        for (int mf = 0; mf < MF; mf++)
            #pragma unroll
            for (int nf = 0; nf < NF; nf++)
                #pragma unroll
                for (int q = 0; q < 4; q++) acc[mf][nf][q] = 0.0f;

        #pragma unroll 2
        for (int s = 0; s < STEPS; s++) {
            const uint32_t ap = (uint32_t)s * (16 * ROWB);
            const uint32_t bp = (uint32_t)s * BPANEL;
            uint32_t a[MF][4], bf[NF][2];
            #pragma unroll
            for (int mf = 0; mf < MF; mf++) ldsm_x4t(a[mf], aoff[mf] + ap);
            #pragma unroll
            for (int p = 0; p < NF / 2; p++) {
                uint32_t rr[4];
                ldsm_x4(rr, boff[p] + bp);
                bf[2 * p][0] = rr[0]; bf[2 * p][1] = rr[1];
                bf[2 * p + 1][0] = rr[2]; bf[2 * p + 1][1] = rr[3];
            }
            ldsm_x2(bf[NF - 1], boff2 + bp);
            #pragma unroll
            for (int mf = 0; mf < MF; mf++)
                #pragma unroll
                for (int nf = 0; nf < NF; nf++)
                    mma_f16(acc[mf][nf], a[mf], bf[nf]);
        }
        __syncthreads();

        if (t + GRID < NTILES) fill(t + GRID);

        const int r  = lid >> 2;
        const int ci = lid & 3;
        #pragma unroll
        for (int nf = 0; nf < NF; nf++) {
            const int o0 = wn * WN + nf * 8 + ci * 2;
            if (o0 < NOUT) {
                const float bi0 = __ldg(bias + o0);
                const float bi1 = __ldg(bias + o0 + 1);
                #pragma unroll
                for (int mf = 0; mf < MF; mf++) {
                    const float* d = acc[mf][nf];
                    #pragma unroll
                    for (int q = 0; q < 4; q++) {
                        const int o  = o0 + (q & 1);
                        const int xg = x0 + wm * WM + mf * 16 + r + (q >> 1) * 8;
                        out_[(((size_t)(b * NOUT + o)) << 16) + (size_t)y * 256 + xg]
                            = d[q] + ((q & 1) ? bi1 : bi0);
                    }
                }
            }
        }

        CP_WAIT0();
        __syncthreads();
    }
}

extern "C" void kernel_launch(void* const* d_in, const int* in_sizes, int n_in,
                              void* d_out, int out_size)
{
    const float* x  = (const float*)d_in[0];
    const float* w1 = (const float*)d_in[1];
    const float* b1 = (const float*)d_in[2];
    const float* w2 = (const float*)d_in[3];
    const float* b2 = (const float*)d_in[4];

    __half *xs, *hs, *w1i, *w2i;
    cudaGetSymbolAddress((void**)&xs, g_xs);
    cudaGetSymbolAddress((void**)&hs, g_hs);
    cudaGetSymbolAddress((void**)&w1i, g_w1i);
    cudaGetSymbolAddress((void**)&w2i, g_w2i);

    cudaFuncSetAttribute(shift_gemm1, cudaFuncAttributeMaxDynamicSharedMemorySize, SMEM_K1);
    cudaFuncSetAttribute(shift_gemm2, cudaFuncAttributeMaxDynamicSharedMemorySize, SMEM_K2);

    prep_x<<<(int)(((size_t)8 * 100 * HW / 4 + NTHR - 1) / NTHR), NTHR>>>(x);
    prep_w<<<64, 256>>>(w1, w2);
    shift_gemm1<<<GRID, NTHR, SMEM_K1>>>(xs, w1i, b1, hs);
    shift_gemm2<<<GRID, NTHR, SMEM_K2>>>(hs, w2i, b2, (float*)d_out);
}

// round 17
// speedup vs baseline: 1.4905x; 1.0315x over previous
#include <cuda_runtime.h>
#include <cuda_fp16.h>
#include <math.h>
#include <stdint.h>

#define NTHR   256
#define GRID   304           // k2: 2 CTAs/SM * 152 SMs
#define K1GRID 456           // k1: 3 CTAs/SM * 152 SMs
#define HW     65536

// ---------------------------------------------------------------------------
// Static device scratch. Planes are PRE-SHIFTED per channel group.
// ---------------------------------------------------------------------------
__device__ __half g_xs[(size_t)8 * 100 * HW];   // shifted x, fp16
__device__ __half g_hs[(size_t)8 * 200 * HW];   // shifted gelu(h), fp16
__device__ __align__(16) __half g_w1i[224 * 112];   // L1 weight image (50176 B)
__device__ __align__(16) __half g_w2i[112 * 208];   // L2 weight image (46592 B)

__host__ __device__ __forceinline__ int swz(int r, int k) {
    return (r >> 3) * 256 + (r & 7) * 32 + ((((k >> 3) ^ (r >> 2)) & 1) << 4) + (k & 7) * 2;
}

__device__ __forceinline__ uint32_t smem_u32(const void* p) {
    uint32_t a;
    asm("{ .reg .u64 t; cvta.to.shared.u64 t, %1; cvt.u32.u64 %0, t; }" : "=r"(a) : "l"(p));
    return a;
}
__device__ __forceinline__ void ldsm_x4t(uint32_t* r, uint32_t a) {
    asm volatile("ldmatrix.sync.aligned.m8n8.x4.trans.shared.b16 {%0,%1,%2,%3}, [%4];"
                 : "=r"(r[0]), "=r"(r[1]), "=r"(r[2]), "=r"(r[3]) : "r"(a));
}
__device__ __forceinline__ void ldsm_x4(uint32_t* r, uint32_t a) {
    asm volatile("ldmatrix.sync.aligned.m8n8.x4.shared.b16 {%0,%1,%2,%3}, [%4];"
                 : "=r"(r[0]), "=r"(r[1]), "=r"(r[2]), "=r"(r[3]) : "r"(a));
}
__device__ __forceinline__ void ldsm_x2(uint32_t* r, uint32_t a) {
    asm volatile("ldmatrix.sync.aligned.m8n8.x2.shared.b16 {%0,%1}, [%2];"
                 : "=r"(r[0]), "=r"(r[1]) : "r"(a));
}
__device__ __forceinline__ void mma_f16(float* d, const uint32_t* a, const uint32_t* b) {
    asm volatile(
        "mma.sync.aligned.m16n8k16.row.col.f32.f16.f16.f32 "
        "{%0,%1,%2,%3}, {%4,%5,%6,%7}, {%8,%9}, {%0,%1,%2,%3};"
        : "+f"(d[0]), "+f"(d[1]), "+f"(d[2]), "+f"(d[3])
        : "r"(a[0]), "r"(a[1]), "r"(a[2]), "r"(a[3]), "r"(b[0]), "r"(b[1]));
}
#define CP_ASYNC16(dst, src, sz) \
    asm volatile("cp.async.cg.shared.global [%0], [%1], 16, %2;" \
                 :: "r"(dst), "l"(src), "r"(sz))
#define CP_COMMIT()  asm volatile("cp.async.commit_group;" ::: "memory")
#define CP_WAIT0()   asm volatile("cp.async.wait_group 0;" ::: "memory")

// Fast GELU: tanh form with HW MUFU.TANH (|h| < 1 regime: <1e-4 abs deviation
// from exact erf form; fp16 rounding dominates the error budget).
__device__ __forceinline__ float gelu_f(float v) {
    float u = v * (0.7978845608028654f + 0.0356774081363001f * v * v);
    float t;
    asm("tanh.approx.f32 %0, %1;" : "=f"(t) : "f"(u));
    float hv = 0.5f * v;
    return fmaf(hv, t, hv);
}
__device__ __forceinline__ uint32_t pack_h2(float lo, float hi) {
    uint32_t r;
    asm("cvt.rn.f16x2.f32 %0, %1, %2;" : "=r"(r) : "f"(hi), "f"(lo));
    return r;
}

// ---------------------------------------------------------------------------
// prep_x: build shifted fp16 plane from fp32 x. EIGHT pixels per thread,
// single STG.128. groups of 20 channels: +x, -x, +y, -y, identity.
// ---------------------------------------------------------------------------
__global__ void prep_x(const float* __restrict__ x) {
    size_t i = (size_t)blockIdx.x * NTHR + threadIdx.x;
    if (i >= (size_t)8 * 100 * HW / 8) return;
    const int x8 = (int)(i & 31) * 8;
    const int y  = (int)(i >> 5) & 255;
    const int cb = (int)(i >> 13);
    const int c  = cb % 100;
    const int g  = c / 20;
    const int dy = (g == 2) - (g == 3);
    const int dx = (g == 0) - (g == 1);
    const int sy = y + dy;
    const float* row = x + (((size_t)cb) << 16) + (size_t)sy * 256;
    uint32_t v[4] = {0, 0, 0, 0};
    #pragma unroll
    for (int j = 0; j < 8; j++) {
        int sx = x8 + j + dx;
        float f = ((unsigned)sy < 256u && (unsigned)sx < 256u) ? row[sx] : 0.0f;
        v[j >> 1] |= (uint32_t)__half_as_ushort(__float2half_rn(f)) << (16 * (j & 1));
    }
    size_t o = (((size_t)cb) << 16) + (size_t)y * 256 + x8;
    *(uint4*)(g_xs + o) = make_uint4(v[0], v[1], v[2], v[3]);
}

__global__ void prep_w(const float* __restrict__ w1, const float* __restrict__ w2) {
    int tid = blockIdx.x * blockDim.x + threadIdx.x;
    int nth = gridDim.x * blockDim.x;
    for (int i = tid; i < 224 * 112; i += nth) {
        int n = i / 112, k = i - n * 112;
        float v = (n < 200 && k < 100) ? w1[n * 100 + k] : 0.0f;
        *(__half*)((char*)g_w1i + (k >> 4) * 7168 + swz(n, k & 15)) = __float2half_rn(v);
    }
    for (int i = tid; i < 112 * 208; i += nth) {
        int n = i / 208, k = i - n * 208;
        float v = (n < 100 && k < 200) ? w2[n * 200 + k] : 0.0f;
        *(__half*)((char*)g_w2i + (k >> 4) * 3584 + swz(n, k & 15)) = __float2half_rn(v);
    }
}

// ---------------------------------------------------------------------------
// k1 TRANSPOSED: A = W1 image (M=224 ch), B = pixel tile (N=64).
// 3 CTAs/SM (85 regs forced: 56 acc + frags fit; cold-path spill only).
// ---------------------------------------------------------------------------
static constexpr int K1_ABYTES = 112 * 128;     // 14336
static constexpr int K1_BBYTES = 50176;
static constexpr int K1_STAGEB = 80 * 68 * 2;   // 10880
static constexpr int SMEM_K1 = K1_ABYTES + K1_BBYTES + K1_STAGEB;  // 75392

__global__ __launch_bounds__(NTHR, 3) void shift_gemm1(
    const __half* __restrict__ ph, const __half* __restrict__ bimg,
    const float* __restrict__ bias, __half* __restrict__ outh)
{
    constexpr int STEPS = 7, CK = 100, SECS = 112;
    constexpr int ROWB = 128, NTILES = 8192;

    extern __shared__ __align__(16) unsigned char smem[];
    const uint32_t sbA = smem_u32(smem);
    const uint32_t sbB = sbA + K1_ABYTES;
    __half* stage = (__half*)(smem + K1_ABYTES + K1_BBYTES);
    const int tid = threadIdx.x, wid = tid >> 5, lid = tid & 31;
    const int wm = wid & 1;        // channel-half warp (0-1)
    const int wn = wid >> 1;       // pixel warp (0-3)

    for (int i = tid * 16; i < K1_BBYTES; i += NTHR * 16)
        *(uint4*)(smem + K1_ABYTES + i) = *(const uint4*)((const char*)bimg + i);

    auto fill = [&](int t) {
        const int x0 = (t & 3) * 64;
        const int y  = (t >> 2) & 255;
        const int b  = t >> 10;
        const size_t pbase = (((size_t)b * CK) << 16) + (size_t)y * 256 + x0;
        for (int j = tid; j < SECS * 8; j += NTHR) {
            const int s = j >> 3, c = j & 7;
            const __half* src = ph + pbase + (((size_t)s) << 16) + c * 8;
            const uint32_t dst = sbA + s * ROWB + (((c ^ (s & 7)) & 7) << 4);
            CP_ASYNC16(dst, src, (s < CK) ? 16 : 0);
        }
        CP_COMMIT();
    };

    // B-frag (activations) lane base: x4t
    const int lg = lid >> 3, lr = lid & 7;
    const int krow = (lg & 1) * 8 + lr;
    const int c0   = wn * 2 + (lg >> 1);
    const uint32_t bA = sbA + (uint32_t)(krow * ROWB) + ((uint32_t)((c0 ^ (krow & 7)) & 7) << 4);

    // A-frag (weights) lane bases: non-trans x4
    const int arow_l = ((lid >> 3) & 1) * 8 + (lid & 7);
    const int kh     = (lid >> 4) & 1;
    uint32_t aoff[7];
    #pragma unroll
    for (int mf = 0; mf < 7; mf++)
        aoff[mf] = sbB + (uint32_t)swz(wm * 112 + mf * 16 + arow_l, kh * 8);

    if ((int)blockIdx.x < NTILES) fill(blockIdx.x);
    CP_WAIT0();
    __syncthreads();

    for (int t = blockIdx.x; t < NTILES; t += K1GRID) {
        const int x0 = (t & 3) * 64;
        const int y  = (t >> 2) & 255;
        const int b  = t >> 10;

        float acc[7][2][4];
        #pragma unroll
        for (int mf = 0; mf < 7; mf++)
            #pragma unroll
            for (int nf = 0; nf < 2; nf++)
                #pragma unroll
                for (int q = 0; q < 4; q++) acc[mf][nf][q] = 0.0f;

        #pragma unroll
        for (int s = 0; s < STEPS; s++) {
            uint32_t bf[4];
            ldsm_x4t(bf, bA + (uint32_t)s * (16 * ROWB));
            #pragma unroll
            for (int mf = 0; mf < 7; mf++) {
                uint32_t a[4];
                ldsm_x4(a, aoff[mf] + (uint32_t)s * 7168);
                mma_f16(acc[mf][0], a, bf + 0);
                mma_f16(acc[mf][1], a, bf + 2);
            }
        }
        __syncthreads();

        if (t + K1GRID < NTILES) fill(t + K1GRID);

        // ---- Epilogue phase 1: fast gelu, pack, direct-store or stage ----
        const int r  = lid >> 2;
        const int pxb = x0 + wn * 16 + 2 * (lid & 3);
        #pragma unroll
        for (int mf = 0; mf < 7; mf++) {
            const int chb = wm * 112 + mf * 16 + r;
            #pragma unroll
            for (int h2 = 0; h2 < 2; h2++) {
                const int ch = chb + 8 * h2;
                if (ch < 200) {
                    const float bi = __ldg(bias + ch);
                    const int g  = ch / 40;
                    const int dx = (g == 0) - (g == 1);
                    const int dy = (g == 2) - (g == 3);
                    #pragma unroll
                    for (int nf = 0; nf < 2; nf++) {
                        const int px = pxb + nf * 8;
                        const float v0 = gelu_f(acc[mf][nf][h2 * 2 + 0] + bi);
                        const float v1 = gelu_f(acc[mf][nf][h2 * 2 + 1] + bi);
                        const uint32_t pk = pack_h2(v0, v1);
                        if (dx == 0) {
                            const size_t base = ((size_t)(b * 200 + ch)) << 16;
                            const int ty = y - dy;
                            if ((unsigned)ty < 256u)
                                *(uint32_t*)(outh + base + (size_t)ty * 256 + px) = pk;
                            if ((dy == 1 && y == 255) || (dy == -1 && y == 0))
                                *(uint32_t*)(outh + base + (size_t)y * 256 + px) = 0u;
                        } else {
                            *(uint32_t*)(stage + ch * 68 + (px - x0)) = pk;
                        }
                    }
                }
            }
        }
        __syncthreads();

        // ---- Epilogue phase 2: flush x-shifted channels (0-79) ----
        for (int ch = wid; ch < 80; ch += 8) {
            const int dx = (ch < 40) ? 1 : -1;
            __half* rowp = outh + (((size_t)(b * 200 + ch)) << 16) + (size_t)y * 256;
            const int txA0 = x0 - dx;
            const int txA = (txA0 < 0) ? 0 : txA0;
            const int txB0 = x0 + 63 - dx;
            const int txB = (txB0 > 255) ? 255 : txB0;
            #pragma unroll
            for (int hh = 0; hh < 2; hh++) {
                const int tx = txA + lid + hh * 32;
                if (tx <= txB)
                    rowp[tx] = stage[ch * 68 + (tx + dx - x0)];
            }
            if (dx == 1 && x0 == 192 && lid == 0) rowp[255] = __ushort_as_half(0);
            if (dx == -1 && x0 == 0  && lid == 0) rowp[0]   = __ushort_as_half(0);
        }

        CP_WAIT0();
        __syncthreads();
    }
}

// ---------------------------------------------------------------------------
// k2: byte-identical to the passing round-13/15 kernel
// ---------------------------------------------------------------------------
static constexpr int SMEM_K2 = 208 * 256 + 46592;   // 99840

__global__ __launch_bounds__(NTHR, 2) void shift_gemm2(
    const __half* __restrict__ ph, const __half* __restrict__ bimg,
    const float* __restrict__ bias, float* __restrict__ out_)
{
    constexpr int CK = 200, SECS = 208, STEPS = 13, NOUT = 100;
    constexpr int MWARPS = 4, MF = 2, BPANEL = 3584, BBYTES = 46592;
    constexpr int NF = 7, WM = 32, WN = 56;
    constexpr int ROWB = 256, NCH = 16, ABYTES = SECS * ROWB;
    constexpr int NTILES = 2 * 256 * 8;

    extern __shared__ __align__(16) unsigned char smem[];
    const uint32_t sbA = smem_u32(smem);
    const uint32_t sbB = sbA + ABYTES;
    const int tid = threadIdx.x, wid = tid >> 5, lid = tid & 31;
    const int wm = wid % MWARPS, wn = wid / MWARPS;

    for (int i = tid * 16; i < BBYTES; i += NTHR * 16)
        *(uint4*)(smem + ABYTES + i) = *(const uint4*)((const char*)bimg + i);

    auto fill = [&](int t) {
        const int x0 = (t & 1) << 7;
        const int y  = (t >> 1) & 255;
        const int b  = t >> 9;
        const size_t pbase = (((size_t)b * CK) << 16) + (size_t)y * 256 + x0;
        for (int j = tid; j < SECS * NCH; j += NTHR) {
            const int s = j / NCH, c = j % NCH;
            const __half* src = ph + pbase + (((size_t)s) << 16) + c * 8;
            const uint32_t dst = sbA + s * ROWB + (((c ^ (s & 7)) & (NCH - 1)) << 4);
            CP_ASYNC16(dst, src, (s < CK) ? 16 : 0);
        }
        CP_COMMIT();
    };

    const int lg = lid >> 3, lr = lid & 7;
    uint32_t aoff[MF];
    #pragma unroll
    for (int mf = 0; mf < MF; mf++) {
        const int m0 = wm * WM + mf * 16 + (lg & 1) * 8;
        aoff[mf] = sbA + (uint32_t)(((lg >> 1) * 8 + lr) * ROWB)
                 + (uint32_t)((((m0 >> 3) ^ lr) & (NCH - 1)) << 4);
    }
    uint32_t boff[NF / 2], boff2;
    {
        const int nrow = ((lid >> 4) & 1) * 8 + (lid & 7);
        const int khb  = (lid >> 3) & 1;
        #pragma unroll
        for (int p = 0; p < NF / 2; p++)
            boff[p] = sbB + swz(wn * WN + p * 16 + nrow, khb * 8);
        boff2 = sbB + swz(wn * WN + (NF / 2) * 16 + (lid & 7), khb * 8);
    }

    if ((int)blockIdx.x < NTILES) fill(blockIdx.x);
    CP_WAIT0();
    __syncthreads();

    for (int t = blockIdx.x; t < NTILES; t += GRID) {
        const int x0 = (t & 1) << 7;
        const int y  = (t >> 1) & 255;
        const int b  = t >> 9;

        float acc[MF][NF][4];
        #pragma unroll
        for (int mf = 0; mf < MF; mf++)
            #pragma unroll
            for (int nf = 0; nf < NF; nf++)
                #pragma unroll
                for (int q = 0; q < 4; q++) acc[mf][nf][q] = 0.0f;

        #pragma unroll 2
        for (int s = 0; s < STEPS; s++) {
            const uint32_t ap = (uint32_t)s * (16 * ROWB);
            const uint32_t bp = (uint32_t)s * BPANEL;
            uint32_t a[MF][4], bf[NF][2];
            #pragma unroll
            for (int mf = 0; mf < MF; mf++) ldsm_x4t(a[mf], aoff[mf] + ap);
            #pragma unroll
            for (int p = 0; p < NF / 2; p++) {
                uint32_t rr[4];
                ldsm_x4(rr, boff[p] + bp);
                bf[2 * p][0] = rr[0]; bf[2 * p][1] = rr[1];
                bf[2 * p + 1][0] = rr[2]; bf[2 * p + 1][1] = rr[3];
            }
            ldsm_x2(bf[NF - 1], boff2 + bp);
            #pragma unroll
            for (int mf = 0; mf < MF; mf++)
                #pragma unroll
                for (int nf = 0; nf < NF; nf++)
                    mma_f16(acc[mf][nf], a[mf], bf[nf]);
        }
        __syncthreads();

        if (t + GRID < NTILES) fill(t + GRID);

        const int r  = lid >> 2;
        const int ci = lid & 3;
        #pragma unroll
        for (int nf = 0; nf < NF; nf++) {
            const int o0 = wn * WN + nf * 8 + ci * 2;
            if (o0 < NOUT) {
                const float bi0 = __ldg(bias + o0);
                const float bi1 = __ldg(bias + o0 + 1);
                #pragma unroll
                for (int mf = 0; mf < MF; mf++) {
                    const float* d = acc[mf][nf];
                    #pragma unroll
                    for (int q = 0; q < 4; q++) {
                        const int o  = o0 + (q & 1);
                        const int xg = x0 + wm * WM + mf * 16 + r + (q >> 1) * 8;
                        out_[(((size_t)(b * NOUT + o)) << 16) + (size_t)y * 256 + xg]
                            = d[q] + ((q & 1) ? bi1 : bi0);
                    }
                }
            }
        }

        CP_WAIT0();
        __syncthreads();
    }
}

extern "C" void kernel_launch(void* const* d_in, const int* in_sizes, int n_in,
                              void* d_out, int out_size)
{
    const float* x  = (const float*)d_in[0];
    const float* w1 = (const float*)d_in[1];
    const float* b1 = (const float*)d_in[2];
    const float* w2 = (const float*)d_in[3];
    const float* b2 = (const float*)d_in[4];

    __half *xs, *hs, *w1i, *w2i;
    cudaGetSymbolAddress((void**)&xs, g_xs);
    cudaGetSymbolAddress((void**)&hs, g_hs);
    cudaGetSymbolAddress((void**)&w1i, g_w1i);
    cudaGetSymbolAddress((void**)&w2i, g_w2i);

    cudaFuncSetAttribute(shift_gemm1, cudaFuncAttributeMaxDynamicSharedMemorySize, SMEM_K1);
    cudaFuncSetAttribute(shift_gemm2, cudaFuncAttributeMaxDynamicSharedMemorySize, SMEM_K2);

    prep_x<<<(int)(((size_t)8 * 100 * HW / 8 + NTHR - 1) / NTHR), NTHR>>>(x);
    prep_w<<<64, 256>>>(w1, w2);
    shift_gemm1<<<K1GRID, NTHR, SMEM_K1>>>(xs, w1i, b1, hs);
    shift_gemm2<<<GRID, NTHR, SMEM_K2>>>(hs, w2i, b2, (float*)d_out);
}